// round 15
// baseline (speedup 1.0000x reference)
#include <cuda_runtime.h>
#include <cuda_fp16.h>
#include <stdint.h>
#include <string.h>

#define N_NODES 100000
#define N_EDGES 1600000
#define BN_EPS  1e-5f

// ---------------------------------------------------------------------------
// Device scratch
// ---------------------------------------------------------------------------
__device__ __align__(16) __half g_x16[(size_t)N_NODES * 64];        // fp16 copy of x
__device__ int g_cnt[N_NODES];        // per-dst edge counts
__device__ int g_off[N_NODES];        // exclusive prefix (segment starts)
__device__ int g_pos[N_NODES];        // running fill pointers
__device__ int g_sorted[N_EDGES];     // src indices grouped by dst
__device__ int g_part[128];           // block partials for scan
// Weight image: 10 K-chunks of 32 (chunks 0-1 = W1, 2-9 = W2), fp16 hi, swizzled.
__device__ __align__(16) unsigned char g_Wimg[163840];
// folded BN: y = v*s + o, then ReLU
__device__ float g_s1[256], g_o1[256], g_s2[256], g_o2[256];

// ---------------------------------------------------------------------------
// Swizzle helpers
// ---------------------------------------------------------------------------
__device__ __forceinline__ uint32_t bswz(int n, int k) {
    int c = (k >> 3) ^ ((n >> 1) & 3);
    return (uint32_t)(n * 64 + c * 16 + (k & 7) * 2);
}
__device__ __forceinline__ uint32_t aswz(int r, int k) {
    int cc = k >> 3;
    int ccp = (cc & 24) | ((cc ^ r) & 7);
    return (uint32_t)(r * 512 + ccp * 16 + (k & 7) * 2);
}

// ---------------------------------------------------------------------------
// Aggregation prep pipeline (counting sort by dst)
// ---------------------------------------------------------------------------
// init16 also zeros the histogram counters
__global__ void k_init16(const float* __restrict__ x) {
    int i = blockIdx.x * blockDim.x + threadIdx.x;
    if (i < N_NODES) g_cnt[i] = 0;
    if (i < N_NODES * 16) {
        float4 v = reinterpret_cast<const float4*>(x)[i];
        __half2 h0 = __floats2half2_rn(v.x, v.y);
        __half2 h1 = __floats2half2_rn(v.z, v.w);
        uint2 p;
        memcpy(&p.x, &h0, 4);
        memcpy(&p.y, &h1, 4);
        reinterpret_cast<uint2*>(g_x16)[i] = p;
    }
}

__global__ void k_hist(const int* __restrict__ ei) {
    int e = blockIdx.x * blockDim.x + threadIdx.x;
    if (e < N_EDGES) atomicAdd(&g_cnt[__ldg(ei + N_EDGES + e)], 1);
}

// Scan step 1: per-block (1024) exclusive prefix + block totals
__global__ void k_scan1() {
    __shared__ int sh[1024];
    int tid = threadIdx.x;
    int i = blockIdx.x * 1024 + tid;
    int v = (i < N_NODES) ? g_cnt[i] : 0;
    sh[tid] = v;
    __syncthreads();
    #pragma unroll
    for (int d = 1; d < 1024; d <<= 1) {
        int t = (tid >= d) ? sh[tid - d] : 0;
        __syncthreads();
        sh[tid] += t;
        __syncthreads();
    }
    if (i < N_NODES) g_off[i] = sh[tid] - v;     // exclusive within block
    if (tid == 1023) g_part[blockIdx.x] = sh[1023];
}

// Scan step 2: exclusive scan of 98 block totals (single block)
__global__ void k_scan2() {
    __shared__ int sh[128];
    int tid = threadIdx.x;
    if (tid < 98) sh[tid] = g_part[tid];
    __syncthreads();
    if (tid == 0) {
        int run = 0;
        for (int i = 0; i < 98; i++) { int t = sh[i]; sh[i] = run; run += t; }
    }
    __syncthreads();
    if (tid < 98) g_part[tid] = sh[tid];
}

// Scan step 3: add block offsets; init fill pointers
__global__ void k_scan3() {
    int i = blockIdx.x * blockDim.x + threadIdx.x;
    if (i < N_NODES) {
        int o = g_off[i] + g_part[i >> 10];
        g_off[i] = o;
        g_pos[i] = o;
    }
}

__global__ void k_reorder(const int* __restrict__ ei) {
    int e = blockIdx.x * blockDim.x + threadIdx.x;
    if (e < N_EDGES) {
        int src = __ldg(ei + e);
        int dst = __ldg(ei + N_EDGES + e);
        int pos = atomicAdd(&g_pos[dst], 1);
        g_sorted[pos] = src;
    }
}

// ---------------------------------------------------------------------------
// Prep: weights -> fp16 hi swizzled chunk images; fold BN
// ---------------------------------------------------------------------------
__global__ void k_prep(const float* __restrict__ W1, const float* __restrict__ W2,
    const float* __restrict__ b1, const float* __restrict__ g1, const float* __restrict__ be1,
    const float* __restrict__ rm1, const float* __restrict__ rv1,
    const float* __restrict__ b2, const float* __restrict__ g2, const float* __restrict__ be2,
    const float* __restrict__ rm2, const float* __restrict__ rv2)
{
    int t = blockIdx.x * 256 + threadIdx.x;
    if (t < 81920) {
        int ci = t >> 13;          // chunk 0..9
        int r  = t & 8191;
        int n  = r >> 5;           // 0..255
        int kl = r & 31;           // 0..31
        float v;
        if (ci < 2) v = W1[(size_t)(ci * 32 + kl) * 256 + n];
        else        v = W2[(size_t)((ci - 2) * 32 + kl) * 256 + n];
        unsigned char* base = g_Wimg + (size_t)ci * 16384;
        *(__half*)(base + bswz(n, kl)) = __float2half_rn(v);
    } else if (t < 82432) {
        int i = t - 81920;
        int n = i & 255;
        if (i < 256) { float s = g1[n] * rsqrtf(rv1[n] + BN_EPS); g_s1[n] = s; g_o1[n] = (b1[n] - rm1[n]) * s + be1[n]; }
        else         { float s = g2[n] * rsqrtf(rv2[n] + BN_EPS); g_s2[n] = s; g_o2[n] = (b2[n] - rm2[n]) * s + be2[n]; }
    }
}

// ---------------------------------------------------------------------------
// PTX helpers (arch-agnostic sm_80+)
// ---------------------------------------------------------------------------
__device__ __forceinline__ uint32_t s2u(const void* p) {
    uint32_t a;
    asm("{ .reg .u64 t; cvta.to.shared.u64 t, %1; cvt.u32.u64 %0, t; }" : "=r"(a) : "l"(p));
    return a;
}
__device__ __forceinline__ void ldm4(uint32_t* r, uint32_t addr) {
    asm volatile("ldmatrix.sync.aligned.m8n8.x4.shared.b16 {%0,%1,%2,%3}, [%4];"
                 : "=r"(r[0]), "=r"(r[1]), "=r"(r[2]), "=r"(r[3]) : "r"(addr));
}
__device__ __forceinline__ void mma_f16(float* c, const uint32_t* a, uint32_t b0, uint32_t b1) {
    asm volatile(
        "mma.sync.aligned.m16n8k16.row.col.f32.f16.f16.f32 "
        "{%0,%1,%2,%3}, {%4,%5,%6,%7}, {%8,%9}, {%0,%1,%2,%3};"
        : "+f"(c[0]), "+f"(c[1]), "+f"(c[2]), "+f"(c[3])
        : "r"(a[0]), "r"(a[1]), "r"(a[2]), "r"(a[3]), "r"(b0), "r"(b1));
}
__device__ __forceinline__ void cpa16(uint32_t s, const void* g) {
    asm volatile("cp.async.cg.shared.global [%0], [%1], 16;" :: "r"(s), "l"(g));
}
#define CP_COMMIT() asm volatile("cp.async.commit_group;" ::: "memory")

// fp16 hi/lo split of a pair of floats, packed as half2 words
__device__ __forceinline__ void split_pack(float a, float b, uint32_t& hi, uint32_t& lo) {
    __half ah = __float2half_rn(a), bh = __float2half_rn(b);
    float ar = a - __half2float(ah);
    float br = b - __half2float(bh);
    __half2 hp = __halves2half2(ah, bh);   // low half = a
    __half2 lp = __floats2half2_rn(ar, br);
    memcpy(&hi, &hp, 4);
    memcpy(&lo, &lp, 4);
}

// ---------------------------------------------------------------------------
// Fused kernel: per-CTA gather-aggregate (GIN sum) + fp16 mma.sync MLP.
// 2-term (hi+lo A) layer 1, single-term layer 2.
// CTA = 64 nodes x 256 cols, 256 threads (8 warps), 2 CTAs/SM.
// Aggregation: warp w handles nodes w*8..w*8+7 serially; lanes parallel over
// 64 cols (half2); identical summation order to the old k_aggregate.
// ---------------------------------------------------------------------------
#define H_LO     32768
#define OFF_B0   65536
#define STAGE_SZ 16384
#define SMEM_REQ (114688 + 128)

__global__ __launch_bounds__(256, 2) void k_mlp6(float* __restrict__ out,
                                                 const float* __restrict__ x) {
    extern __shared__ unsigned char dyn[];
    uint32_t raw = s2u(dyn);
    uint32_t sb  = (raw + 127u) & ~127u;
    unsigned char* sp = dyn + (sb - raw);

    const int tid  = threadIdx.x;
    const int lane = tid & 31;
    const int w    = tid >> 5;
    const int m_w  = (w >> 2) * 32;
    const int n_w  = (w & 3) * 64;
    const int lr   = lane & 7, lsel = lane >> 3;
    const int arow = lr + (lsel & 1) * 8, acol8 = (lsel >> 1) * 8;
    const int brow = lr + (lsel >> 1) * 8, bcol8 = (lsel & 1) * 8;
    const int gid  = lane >> 2, tg2 = (lane & 3) * 2;
    const int row0 = blockIdx.x * 64;

    // ---- prologue: prefetch chunks 0,1 into stages 0,1 (16KB each) ----
    #pragma unroll
    for (int j = 0; j < 4; j++)
        cpa16(sb + OFF_B0 + (tid + 256 * j) * 16, g_Wimg + (tid + 256 * j) * 16);
    CP_COMMIT();
    #pragma unroll
    for (int j = 0; j < 4; j++)
        cpa16(sb + OFF_B0 + STAGE_SZ + (tid + 256 * j) * 16,
              g_Wimg + STAGE_SZ + (tid + 256 * j) * 16);
    CP_COMMIT();

    // ---- fused aggregation: h = x + sum_nbrs fp16(x), straight into A planes ----
    {
        const uint32_t* xr = (const uint32_t*)g_x16;   // row = 32 uints
        for (int t = 0; t < 8; t++) {
            int rloc = w * 8 + t;            // 0..63
            int n = row0 + rloc;
            float ax = 0.f, ay = 0.f;
            if (n < N_NODES) {
                int off = __ldg(g_off + n);
                int cnt = __ldg(g_cnt + n);
                for (int base = 0; base < cnt; base += 32) {
                    int rem = cnt - base; if (rem > 32) rem = 32;
                    int s = (lane < rem) ? __ldg(g_sorted + off + base + lane) : 0;
                    int j = 0;
                    for (; j + 4 <= rem; j += 4) {
                        int s0 = __shfl_sync(0xffffffffu, s, j);
                        int s1 = __shfl_sync(0xffffffffu, s, j + 1);
                        int s2 = __shfl_sync(0xffffffffu, s, j + 2);
                        int s3 = __shfl_sync(0xffffffffu, s, j + 3);
                        uint32_t p0 = __ldg(xr + (size_t)s0 * 32 + lane);
                        uint32_t p1 = __ldg(xr + (size_t)s1 * 32 + lane);
                        uint32_t p2 = __ldg(xr + (size_t)s2 * 32 + lane);
                        uint32_t p3 = __ldg(xr + (size_t)s3 * 32 + lane);
                        __half2 h; float2 f;
                        memcpy(&h, &p0, 4); f = __half22float2(h); ax += f.x; ay += f.y;
                        memcpy(&h, &p1, 4); f = __half22float2(h); ax += f.x; ay += f.y;
                        memcpy(&h, &p2, 4); f = __half22float2(h); ax += f.x; ay += f.y;
                        memcpy(&h, &p3, 4); f = __half22float2(h); ax += f.x; ay += f.y;
                    }
                    for (; j < rem; j++) {
                        int sj = __shfl_sync(0xffffffffu, s, j);
                        uint32_t p = __ldg(xr + (size_t)sj * 32 + lane);
                        __half2 h; memcpy(&h, &p, 4);
                        float2 f = __half22float2(h);
                        ax += f.x; ay += f.y;
                    }
                }
                float2 xv = *(const float2*)(x + (size_t)n * 64 + lane * 2);
                ax += xv.x; ay += xv.y;
            }
            uint32_t hi, lo;
            split_pack(ax, ay, hi, lo);
            uint32_t o = aswz(rloc, lane * 2);
            *(uint32_t*)(sp + o)        = hi;
            *(uint32_t*)(sp + H_LO + o) = lo;
        }
    }

    float acc[2][8][4];
    #pragma unroll
    for (int a = 0; a < 2; a++)
        #pragma unroll
        for (int b = 0; b < 8; b++)
            #pragma unroll
            for (int cq = 0; cq < 4; cq++) acc[a][b][cq] = 0.f;

    __syncthreads();   // A planes ready (also covers weight-stage visibility order)

    for (int i = 0; i < 10; i++) {
        if (i < 9) asm volatile("cp.async.wait_group 1;" ::: "memory");
        else       asm volatile("cp.async.wait_group 0;" ::: "memory");
        __syncthreads();

        if (i + 2 <= 9) {
            const unsigned char* g = g_Wimg + (size_t)(i + 2) * STAGE_SZ;
            uint32_t s = sb + OFF_B0 + ((i + 2) % 3) * STAGE_SZ;
            #pragma unroll
            for (int j = 0; j < 4; j++)
                cpa16(s + (tid + 256 * j) * 16, g + (tid + 256 * j) * 16);
            CP_COMMIT();
        }

        const bool l1 = (i < 2);
        const int kA0 = l1 ? i * 32 : (i - 2) * 32;
        const uint32_t bbuf = sb + OFF_B0 + (i % 3) * STAGE_SZ;

        #pragma unroll
        for (int step = 0; step < 2; step++) {
            const int kA = kA0 + step * 16;
            const int kB = step * 16;
            uint32_t Ah[2][4], Al[2][4], Bb[4][4];
            #pragma unroll
            for (int mt = 0; mt < 2; mt++)
                ldm4(Ah[mt], sb + aswz(m_w + mt * 16 + arow, kA + acol8));
            if (l1) {
                #pragma unroll
                for (int mt = 0; mt < 2; mt++)
                    ldm4(Al[mt], sb + H_LO + aswz(m_w + mt * 16 + arow, kA + acol8));
            }
            #pragma unroll
            for (int np = 0; np < 4; np++)
                ldm4(Bb[np], bbuf + bswz(n_w + np * 16 + brow, kB + bcol8));
            // hi * hi
            #pragma unroll
            for (int mt = 0; mt < 2; mt++)
                #pragma unroll
                for (int np = 0; np < 4; np++) {
                    mma_f16(acc[mt][np * 2],     Ah[mt], Bb[np][0], Bb[np][1]);
                    mma_f16(acc[mt][np * 2 + 1], Ah[mt], Bb[np][2], Bb[np][3]);
                }
            // lo * hi (layer 1 only)
            if (l1) {
                #pragma unroll
                for (int mt = 0; mt < 2; mt++)
                    #pragma unroll
                    for (int np = 0; np < 4; np++) {
                        mma_f16(acc[mt][np * 2],     Al[mt], Bb[np][0], Bb[np][1]);
                        mma_f16(acc[mt][np * 2 + 1], Al[mt], Bb[np][2], Bb[np][3]);
                    }
            }
        }

        if (i == 1) {
            __syncthreads();
            // ---- epilogue 1: BN1 + ReLU -> H1 hi plane only (layer 2 is
            //      single-term; lo plane writes are dead), reset acc ----
            #pragma unroll
            for (int nt = 0; nt < 8; nt++) {
                int col = n_w + nt * 8 + tg2;
                float2 s = *(const float2*)(g_s1 + col);
                float2 o = *(const float2*)(g_o1 + col);
                #pragma unroll
                for (int mt = 0; mt < 2; mt++) {
                    float* c = acc[mt][nt];
                    __half2 p0 = __floats2half2_rn(fmaxf(c[0] * s.x + o.x, 0.f),
                                                   fmaxf(c[1] * s.y + o.y, 0.f));
                    __half2 p1 = __floats2half2_rn(fmaxf(c[2] * s.x + o.x, 0.f),
                                                   fmaxf(c[3] * s.y + o.y, 0.f));
                    uint32_t h0, h1;
                    memcpy(&h0, &p0, 4);
                    memcpy(&h1, &p1, 4);
                    int r0 = m_w + mt * 16 + gid;
                    *(uint32_t*)(sp + aswz(r0, col))     = h0;
                    *(uint32_t*)(sp + aswz(r0 + 8, col)) = h1;
                    c[0] = c[1] = c[2] = c[3] = 0.f;
                }
            }
        }
    }

    // ---- epilogue 2: BN2 + ReLU, staged coalesced stores ----
    float* stageF = (float*)(sp + OFF_B0);
    for (int q = 0; q < 2; q++) {
        __syncthreads();
        if ((w >> 2) == q) {
            #pragma unroll
            for (int nt = 0; nt < 8; nt++) {
                int col = n_w + nt * 8 + tg2;
                float2 s = *(const float2*)(g_s2 + col);
                float2 o = *(const float2*)(g_o2 + col);
                #pragma unroll
                for (int mt = 0; mt < 2; mt++) {
                    float* c = acc[mt][nt];
                    int r = mt * 16 + gid;
                    *(float2*)(stageF + r * 260 + col) =
                        make_float2(fmaxf(c[0] * s.x + o.x, 0.f),
                                    fmaxf(c[1] * s.y + o.y, 0.f));
                    *(float2*)(stageF + (r + 8) * 260 + col) =
                        make_float2(fmaxf(c[2] * s.x + o.x, 0.f),
                                    fmaxf(c[3] * s.y + o.y, 0.f));
                }
            }
        }
        __syncthreads();
        #pragma unroll
        for (int j = 0; j < 8; j++) {
            int idx = tid + 256 * j;
            int rr = idx >> 6, c4 = idx & 63;
            int grow = row0 + q * 32 + rr;
            if (grow < N_NODES)
                ((float4*)out)[(size_t)grow * 64 + c4] =
                    *(float4*)(stageF + rr * 260 + c4 * 4);
        }
    }
}

// ---------------------------------------------------------------------------
// Launch
// ---------------------------------------------------------------------------
extern "C" void kernel_launch(void* const* d_in, const int* in_sizes, int n_in,
                              void* d_out, int out_size) {
    const float* x   = (const float*)d_in[0];
    const int*   ei  = (const int*)  d_in[2];
    const float* W1  = (const float*)d_in[3];
    const float* b1  = (const float*)d_in[4];
    const float* g1  = (const float*)d_in[5];
    const float* be1 = (const float*)d_in[6];
    const float* rm1 = (const float*)d_in[7];
    const float* rv1 = (const float*)d_in[8];
    const float* W2  = (const float*)d_in[9];
    const float* b2  = (const float*)d_in[10];
    const float* g2  = (const float*)d_in[11];
    const float* be2 = (const float*)d_in[12];
    const float* rm2 = (const float*)d_in[13];
    const float* rv2 = (const float*)d_in[14];
    float* out = (float*)d_out;

    k_init16<<<(N_NODES * 16 + 255) / 256, 256>>>(x);   // also zeros g_cnt
    k_hist<<<N_EDGES / 256, 256>>>(ei);
    k_prep<<<322, 256>>>(W1, W2, b1, g1, be1, rm1, rv1, b2, g2, be2, rm2, rv2);
    k_scan1<<<98, 1024>>>();
    k_scan2<<<1, 128>>>();
    k_scan3<<<(N_NODES + 255) / 256, 256>>>();
    k_reorder<<<N_EDGES / 256, 256>>>(ei);

    {
        cudaFuncSetAttribute(k_mlp6, cudaFuncAttributeMaxDynamicSharedMemorySize,
                             SMEM_REQ);
        int blocks = (N_NODES + 63) / 64;   // 1563
        k_mlp6<<<blocks, 256, SMEM_REQ>>>(out, x);
    }
    (void)in_sizes; (void)n_in; (void)out_size;
}

// round 16
// speedup vs baseline: 1.4381x; 1.4381x over previous
#include <cuda_runtime.h>
#include <cuda_fp16.h>
#include <stdint.h>
#include <string.h>

#define N_NODES 100000
#define N_EDGES 1600000
#define BN_EPS  1e-5f

// ---------------------------------------------------------------------------
// Device scratch
// ---------------------------------------------------------------------------
__device__ __align__(16) float g_aggr[(size_t)N_NODES * 64];        // h = x + sum
__device__ __align__(16) __half g_x16[(size_t)N_NODES * 64];        // fp16 copy of x
__device__ int g_cnt[N_NODES];        // per-dst edge counts
__device__ int g_off[N_NODES];        // exclusive prefix (segment starts)
__device__ int g_pos[N_NODES];        // running fill pointers
__device__ int g_sorted[N_EDGES];     // src indices grouped by dst
__device__ int g_part[128];           // block partials for scan
// Weight image: 10 K-chunks of 32 (chunks 0-1 = W1, 2-9 = W2), fp16 hi, swizzled.
__device__ __align__(16) unsigned char g_Wimg[163840];
// folded BN: y = v*s + o, then ReLU
__device__ float g_s1[256], g_o1[256], g_s2[256], g_o2[256];

// ---------------------------------------------------------------------------
// Swizzle helpers
// ---------------------------------------------------------------------------
__device__ __forceinline__ uint32_t bswz(int n, int k) {
    int c = (k >> 3) ^ ((n >> 1) & 3);
    return (uint32_t)(n * 64 + c * 16 + (k & 7) * 2);
}
__device__ __forceinline__ uint32_t aswz(int r, int k) {
    int cc = k >> 3;
    int ccp = (cc & 24) | ((cc ^ r) & 7);
    return (uint32_t)(r * 512 + ccp * 16 + (k & 7) * 2);
}

// ---------------------------------------------------------------------------
// Aggregation pipeline (counting sort by dst, then gather-aggregate)
// ---------------------------------------------------------------------------
// init16 also zeros the histogram counters
__global__ void k_init16(const float* __restrict__ x) {
    int i = blockIdx.x * blockDim.x + threadIdx.x;
    if (i < N_NODES) g_cnt[i] = 0;
    if (i < N_NODES * 16) {
        float4 v = reinterpret_cast<const float4*>(x)[i];
        __half2 h0 = __floats2half2_rn(v.x, v.y);
        __half2 h1 = __floats2half2_rn(v.z, v.w);
        uint2 p;
        memcpy(&p.x, &h0, 4);
        memcpy(&p.y, &h1, 4);
        reinterpret_cast<uint2*>(g_x16)[i] = p;
    }
}

__global__ void k_hist(const int* __restrict__ ei) {
    int e = blockIdx.x * blockDim.x + threadIdx.x;
    if (e < N_EDGES) atomicAdd(&g_cnt[__ldg(ei + N_EDGES + e)], 1);
}

// Scan step 1: per-block (1024) exclusive prefix + block totals
__global__ void k_scan1() {
    __shared__ int sh[1024];
    int tid = threadIdx.x;
    int i = blockIdx.x * 1024 + tid;
    int v = (i < N_NODES) ? g_cnt[i] : 0;
    sh[tid] = v;
    __syncthreads();
    #pragma unroll
    for (int d = 1; d < 1024; d <<= 1) {
        int t = (tid >= d) ? sh[tid - d] : 0;
        __syncthreads();
        sh[tid] += t;
        __syncthreads();
    }
    if (i < N_NODES) g_off[i] = sh[tid] - v;     // exclusive within block
    if (tid == 1023) g_part[blockIdx.x] = sh[1023];
}

// Scan step 2: exclusive scan of 98 block totals (single block)
__global__ void k_scan2() {
    __shared__ int sh[128];
    int tid = threadIdx.x;
    if (tid < 98) sh[tid] = g_part[tid];
    __syncthreads();
    if (tid == 0) {
        int run = 0;
        for (int i = 0; i < 98; i++) { int t = sh[i]; sh[i] = run; run += t; }
    }
    __syncthreads();
    if (tid < 98) g_part[tid] = sh[tid];
}

// Scan step 3: add block offsets; init fill pointers
__global__ void k_scan3() {
    int i = blockIdx.x * blockDim.x + threadIdx.x;
    if (i < N_NODES) {
        int o = g_off[i] + g_part[i >> 10];
        g_off[i] = o;
        g_pos[i] = o;
    }
}

__global__ void k_reorder(const int* __restrict__ ei) {
    int e = blockIdx.x * blockDim.x + threadIdx.x;
    if (e < N_EDGES) {
        int src = __ldg(ei + e);
        int dst = __ldg(ei + N_EDGES + e);
        int pos = atomicAdd(&g_pos[dst], 1);
        g_sorted[pos] = src;
    }
}

// One warp per node: gather fp16 rows of all in-neighbors, sum fp32, add x, store h.
// 8-deep software pipeline (MLP=8); accumulation order identical to 4-deep version.
__global__ __launch_bounds__(256) void k_aggregate(const float* __restrict__ x) {
    int n = blockIdx.x * 8 + (threadIdx.x >> 5);   // 12500*8 = 100000 exactly
    int lane = threadIdx.x & 31;
    int off = g_off[n];
    int cnt = g_cnt[n];
    float ax = 0.f, ay = 0.f;
    const uint32_t* xr = (const uint32_t*)g_x16;   // row = 32 uints (64 halves)

    for (int base = 0; base < cnt; base += 32) {
        int rem = cnt - base; if (rem > 32) rem = 32;
        int s = (lane < rem) ? __ldg(g_sorted + off + base + lane) : 0;
        int j = 0;
        for (; j + 8 <= rem; j += 8) {
            uint32_t p[8];
            #pragma unroll
            for (int u = 0; u < 8; u++) {
                int su = __shfl_sync(0xffffffffu, s, j + u);
                p[u] = __ldg(xr + (size_t)su * 32 + lane);
            }
            #pragma unroll
            for (int u = 0; u < 8; u++) {
                __half2 h; memcpy(&h, &p[u], 4);
                float2 f = __half22float2(h);
                ax += f.x; ay += f.y;
            }
        }
        for (; j + 4 <= rem; j += 4) {
            uint32_t p[4];
            #pragma unroll
            for (int u = 0; u < 4; u++) {
                int su = __shfl_sync(0xffffffffu, s, j + u);
                p[u] = __ldg(xr + (size_t)su * 32 + lane);
            }
            #pragma unroll
            for (int u = 0; u < 4; u++) {
                __half2 h; memcpy(&h, &p[u], 4);
                float2 f = __half22float2(h);
                ax += f.x; ay += f.y;
            }
        }
        for (; j < rem; j++) {
            int sj = __shfl_sync(0xffffffffu, s, j);
            uint32_t p = __ldg(xr + (size_t)sj * 32 + lane);
            __half2 h; memcpy(&h, &p, 4);
            float2 f = __half22float2(h);
            ax += f.x; ay += f.y;
        }
    }
    float2 xv = *(const float2*)(x + (size_t)n * 64 + lane * 2);
    *(float2*)(g_aggr + (size_t)n * 64 + lane * 2) =
        make_float2(ax + xv.x, ay + xv.y);
}

// ---------------------------------------------------------------------------
// Prep: weights -> fp16 hi swizzled chunk images; fold BN
// ---------------------------------------------------------------------------
__global__ void k_prep(const float* __restrict__ W1, const float* __restrict__ W2,
    const float* __restrict__ b1, const float* __restrict__ g1, const float* __restrict__ be1,
    const float* __restrict__ rm1, const float* __restrict__ rv1,
    const float* __restrict__ b2, const float* __restrict__ g2, const float* __restrict__ be2,
    const float* __restrict__ rm2, const float* __restrict__ rv2)
{
    int t = blockIdx.x * 256 + threadIdx.x;
    if (t < 81920) {
        int ci = t >> 13;          // chunk 0..9
        int r  = t & 8191;
        int n  = r >> 5;           // 0..255
        int kl = r & 31;           // 0..31
        float v;
        if (ci < 2) v = W1[(size_t)(ci * 32 + kl) * 256 + n];
        else        v = W2[(size_t)((ci - 2) * 32 + kl) * 256 + n];
        unsigned char* base = g_Wimg + (size_t)ci * 16384;
        *(__half*)(base + bswz(n, kl)) = __float2half_rn(v);
    } else if (t < 82432) {
        int i = t - 81920;
        int n = i & 255;
        if (i < 256) { float s = g1[n] * rsqrtf(rv1[n] + BN_EPS); g_s1[n] = s; g_o1[n] = (b1[n] - rm1[n]) * s + be1[n]; }
        else         { float s = g2[n] * rsqrtf(rv2[n] + BN_EPS); g_s2[n] = s; g_o2[n] = (b2[n] - rm2[n]) * s + be2[n]; }
    }
}

// ---------------------------------------------------------------------------
// PTX helpers (arch-agnostic sm_80+)
// ---------------------------------------------------------------------------
__device__ __forceinline__ uint32_t s2u(const void* p) {
    uint32_t a;
    asm("{ .reg .u64 t; cvta.to.shared.u64 t, %1; cvt.u32.u64 %0, t; }" : "=r"(a) : "l"(p));
    return a;
}
__device__ __forceinline__ void ldm4(uint32_t* r, uint32_t addr) {
    asm volatile("ldmatrix.sync.aligned.m8n8.x4.shared.b16 {%0,%1,%2,%3}, [%4];"
                 : "=r"(r[0]), "=r"(r[1]), "=r"(r[2]), "=r"(r[3]) : "r"(addr));
}
__device__ __forceinline__ void mma_f16(float* c, const uint32_t* a, uint32_t b0, uint32_t b1) {
    asm volatile(
        "mma.sync.aligned.m16n8k16.row.col.f32.f16.f16.f32 "
        "{%0,%1,%2,%3}, {%4,%5,%6,%7}, {%8,%9}, {%0,%1,%2,%3};"
        : "+f"(c[0]), "+f"(c[1]), "+f"(c[2]), "+f"(c[3])
        : "r"(a[0]), "r"(a[1]), "r"(a[2]), "r"(a[3]), "r"(b0), "r"(b1));
}
__device__ __forceinline__ void cpa16(uint32_t s, const void* g) {
    asm volatile("cp.async.cg.shared.global [%0], [%1], 16;" :: "r"(s), "l"(g));
}
#define CP_COMMIT() asm volatile("cp.async.commit_group;" ::: "memory")

// fp16 hi/lo split of a pair of floats, packed as half2 words
__device__ __forceinline__ void split_pack(float a, float b, uint32_t& hi, uint32_t& lo) {
    __half ah = __float2half_rn(a), bh = __float2half_rn(b);
    float ar = a - __half2float(ah);
    float br = b - __half2float(bh);
    __half2 hp = __halves2half2(ah, bh);   // low half = a
    __half2 lp = __floats2half2_rn(ar, br);
    memcpy(&hi, &hp, 4);
    memcpy(&lo, &lp, 4);
}

// ---------------------------------------------------------------------------
// Kernel: fp16 mma.sync MLP. 2-term (hi+lo A) layer 1, single-term layer 2.
// CTA = 64 nodes x 256 cols, 256 threads (8 warps), 2 CTAs/SM.
// ---------------------------------------------------------------------------
#define H_LO     32768
#define OFF_B0   65536
#define STAGE_SZ 16384
#define SMEM_REQ (114688 + 128)

__global__ __launch_bounds__(256, 2) void k_mlp6(float* __restrict__ out) {
    extern __shared__ unsigned char dyn[];
    uint32_t raw = s2u(dyn);
    uint32_t sb  = (raw + 127u) & ~127u;
    unsigned char* sp = dyn + (sb - raw);

    const int tid  = threadIdx.x;
    const int lane = tid & 31;
    const int w    = tid >> 5;
    const int m_w  = (w >> 2) * 32;
    const int n_w  = (w & 3) * 64;
    const int lr   = lane & 7, lsel = lane >> 3;
    const int arow = lr + (lsel & 1) * 8, acol8 = (lsel >> 1) * 8;
    const int brow = lr + (lsel >> 1) * 8, bcol8 = (lsel & 1) * 8;
    const int gid  = lane >> 2, tg2 = (lane & 3) * 2;
    const int row0 = blockIdx.x * 64;

    // ---- prologue: prefetch chunks 0,1 into stages 0,1 (16KB each) ----
    #pragma unroll
    for (int j = 0; j < 4; j++)
        cpa16(sb + OFF_B0 + (tid + 256 * j) * 16, g_Wimg + (tid + 256 * j) * 16);
    CP_COMMIT();
    #pragma unroll
    for (int j = 0; j < 4; j++)
        cpa16(sb + OFF_B0 + STAGE_SZ + (tid + 256 * j) * 16,
              g_Wimg + STAGE_SZ + (tid + 256 * j) * 16);
    CP_COMMIT();

    // ---- load h tile [64][64] f32 -> fp16 hi/lo into A/H planes ----
    {
        int rr = tid >> 2, q = tid & 3;
        float4 f[4];
        #pragma unroll
        for (int i = 0; i < 4; i++) {
            f[i] = make_float4(0.f, 0.f, 0.f, 0.f);
            if (row0 + rr < N_NODES)
                f[i] = ((const float4*)g_aggr)[(size_t)(row0 + rr) * 16 + q * 4 + i];
        }
        uint32_t hi[8], lo[8];
        #pragma unroll
        for (int i = 0; i < 4; i++) {
            split_pack(f[i].x, f[i].y, hi[2 * i],     lo[2 * i]);
            split_pack(f[i].z, f[i].w, hi[2 * i + 1], lo[2 * i + 1]);
        }
        uint32_t o0 = aswz(rr, q * 16);
        uint32_t o1 = aswz(rr, q * 16 + 8);
        *(uint4*)(sp + o0)        = ((uint4*)hi)[0];
        *(uint4*)(sp + o1)        = ((uint4*)hi)[1];
        *(uint4*)(sp + H_LO + o0) = ((uint4*)lo)[0];
        *(uint4*)(sp + H_LO + o1) = ((uint4*)lo)[1];
    }

    float acc[2][8][4];
    #pragma unroll
    for (int a = 0; a < 2; a++)
        #pragma unroll
        for (int b = 0; b < 8; b++)
            #pragma unroll
            for (int cq = 0; cq < 4; cq++) acc[a][b][cq] = 0.f;

    for (int i = 0; i < 10; i++) {
        if (i < 9) asm volatile("cp.async.wait_group 1;" ::: "memory");
        else       asm volatile("cp.async.wait_group 0;" ::: "memory");
        __syncthreads();

        if (i + 2 <= 9) {
            const unsigned char* g = g_Wimg + (size_t)(i + 2) * STAGE_SZ;
            uint32_t s = sb + OFF_B0 + ((i + 2) % 3) * STAGE_SZ;
            #pragma unroll
            for (int j = 0; j < 4; j++)
                cpa16(s + (tid + 256 * j) * 16, g + (tid + 256 * j) * 16);
            CP_COMMIT();
        }

        const bool l1 = (i < 2);
        const int kA0 = l1 ? i * 32 : (i - 2) * 32;
        const uint32_t bbuf = sb + OFF_B0 + (i % 3) * STAGE_SZ;

        #pragma unroll
        for (int step = 0; step < 2; step++) {
            const int kA = kA0 + step * 16;
            const int kB = step * 16;
            uint32_t Ah[2][4], Al[2][4], Bb[4][4];
            #pragma unroll
            for (int mt = 0; mt < 2; mt++)
                ldm4(Ah[mt], sb + aswz(m_w + mt * 16 + arow, kA + acol8));
            if (l1) {
                #pragma unroll
                for (int mt = 0; mt < 2; mt++)
                    ldm4(Al[mt], sb + H_LO + aswz(m_w + mt * 16 + arow, kA + acol8));
            }
            #pragma unroll
            for (int np = 0; np < 4; np++)
                ldm4(Bb[np], bbuf + bswz(n_w + np * 16 + brow, kB + bcol8));
            // hi * hi
            #pragma unroll
            for (int mt = 0; mt < 2; mt++)
                #pragma unroll
                for (int np = 0; np < 4; np++) {
                    mma_f16(acc[mt][np * 2],     Ah[mt], Bb[np][0], Bb[np][1]);
                    mma_f16(acc[mt][np * 2 + 1], Ah[mt], Bb[np][2], Bb[np][3]);
                }
            // lo * hi (layer 1 only)
            if (l1) {
                #pragma unroll
                for (int mt = 0; mt < 2; mt++)
                    #pragma unroll
                    for (int np = 0; np < 4; np++) {
                        mma_f16(acc[mt][np * 2],     Al[mt], Bb[np][0], Bb[np][1]);
                        mma_f16(acc[mt][np * 2 + 1], Al[mt], Bb[np][2], Bb[np][3]);
                    }
            }
        }

        if (i == 1) {
            __syncthreads();
            // ---- epilogue 1: BN1 + ReLU -> H1 hi plane only, reset acc ----
            #pragma unroll
            for (int nt = 0; nt < 8; nt++) {
                int col = n_w + nt * 8 + tg2;
                float2 s = *(const float2*)(g_s1 + col);
                float2 o = *(const float2*)(g_o1 + col);
                #pragma unroll
                for (int mt = 0; mt < 2; mt++) {
                    float* c = acc[mt][nt];
                    __half2 p0 = __floats2half2_rn(fmaxf(c[0] * s.x + o.x, 0.f),
                                                   fmaxf(c[1] * s.y + o.y, 0.f));
                    __half2 p1 = __floats2half2_rn(fmaxf(c[2] * s.x + o.x, 0.f),
                                                   fmaxf(c[3] * s.y + o.y, 0.f));
                    uint32_t h0, h1;
                    memcpy(&h0, &p0, 4);
                    memcpy(&h1, &p1, 4);
                    int r0 = m_w + mt * 16 + gid;
                    *(uint32_t*)(sp + aswz(r0, col))     = h0;
                    *(uint32_t*)(sp + aswz(r0 + 8, col)) = h1;
                    c[0] = c[1] = c[2] = c[3] = 0.f;
                }
            }
        }
    }

    // ---- epilogue 2: BN2 + ReLU, staged coalesced stores ----
    float* stageF = (float*)(sp + OFF_B0);
    for (int q = 0; q < 2; q++) {
        __syncthreads();
        if ((w >> 2) == q) {
            #pragma unroll
            for (int nt = 0; nt < 8; nt++) {
                int col = n_w + nt * 8 + tg2;
                float2 s = *(const float2*)(g_s2 + col);
                float2 o = *(const float2*)(g_o2 + col);
                #pragma unroll
                for (int mt = 0; mt < 2; mt++) {
                    float* c = acc[mt][nt];
                    int r = mt * 16 + gid;
                    *(float2*)(stageF + r * 260 + col) =
                        make_float2(fmaxf(c[0] * s.x + o.x, 0.f),
                                    fmaxf(c[1] * s.y + o.y, 0.f));
                    *(float2*)(stageF + (r + 8) * 260 + col) =
                        make_float2(fmaxf(c[2] * s.x + o.x, 0.f),
                                    fmaxf(c[3] * s.y + o.y, 0.f));
                }
            }
        }
        __syncthreads();
        #pragma unroll
        for (int j = 0; j < 8; j++) {
            int idx = tid + 256 * j;
            int rr = idx >> 6, c4 = idx & 63;
            int grow = row0 + q * 32 + rr;
            if (grow < N_NODES)
                ((float4*)out)[(size_t)grow * 64 + c4] =
                    *(float4*)(stageF + rr * 260 + c4 * 4);
        }
    }
}

// ---------------------------------------------------------------------------
// Launch
// ---------------------------------------------------------------------------
extern "C" void kernel_launch(void* const* d_in, const int* in_sizes, int n_in,
                              void* d_out, int out_size) {
    const float* x   = (const float*)d_in[0];
    const int*   ei  = (const int*)  d_in[2];
    const float* W1  = (const float*)d_in[3];
    const float* b1  = (const float*)d_in[4];
    const float* g1  = (const float*)d_in[5];
    const float* be1 = (const float*)d_in[6];
    const float* rm1 = (const float*)d_in[7];
    const float* rv1 = (const float*)d_in[8];
    const float* W2  = (const float*)d_in[9];
    const float* b2  = (const float*)d_in[10];
    const float* g2  = (const float*)d_in[11];
    const float* be2 = (const float*)d_in[12];
    const float* rm2 = (const float*)d_in[13];
    const float* rv2 = (const float*)d_in[14];
    float* out = (float*)d_out;

    k_init16<<<(N_NODES * 16 + 255) / 256, 256>>>(x);   // also zeros g_cnt
    k_hist<<<N_EDGES / 256, 256>>>(ei);
    k_prep<<<322, 256>>>(W1, W2, b1, g1, be1, rm1, rv1, b2, g2, be2, rm2, rv2);
    k_scan1<<<98, 1024>>>();
    k_scan2<<<1, 128>>>();
    k_scan3<<<(N_NODES + 255) / 256, 256>>>();
    k_reorder<<<N_EDGES / 256, 256>>>(ei);
    k_aggregate<<<N_NODES / 8, 256>>>(x);

    {
        cudaFuncSetAttribute(k_mlp6, cudaFuncAttributeMaxDynamicSharedMemorySize,
                             SMEM_REQ);
        int blocks = (N_NODES + 63) / 64;   // 1563
        k_mlp6<<<blocks, 256, SMEM_REQ>>>(out);
    }
    (void)in_sizes; (void)n_in; (void)out_size;
}

// round 17
// speedup vs baseline: 1.4386x; 1.0004x over previous
#include <cuda_runtime.h>
#include <cuda_fp16.h>
#include <stdint.h>
#include <string.h>

#define N_NODES 100000
#define N_EDGES 1600000
#define BN_EPS  1e-5f

// ---------------------------------------------------------------------------
// Device scratch
// ---------------------------------------------------------------------------
__device__ __align__(16) float g_aggr[(size_t)N_NODES * 64];        // h = x + sum
__device__ __align__(16) __half g_x16[(size_t)N_NODES * 64];        // fp16 copy of x
__device__ int g_cnt[N_NODES];        // per-dst edge counts
__device__ int g_off[N_NODES];        // exclusive prefix (segment starts)
__device__ int g_pos[N_NODES];        // running fill pointers
__device__ int g_sorted[N_EDGES];     // src indices grouped by dst
__device__ int g_part[128];           // block partials for scan
// Weight image: 10 K-chunks of 32 (chunks 0-1 = W1, 2-9 = W2), fp16 hi, swizzled.
__device__ __align__(16) unsigned char g_Wimg[163840];
// folded BN: y = v*s + o, then ReLU
__device__ float g_s1[256], g_o1[256], g_s2[256], g_o2[256];

// ---------------------------------------------------------------------------
// Swizzle helpers
// ---------------------------------------------------------------------------
__device__ __forceinline__ uint32_t bswz(int n, int k) {
    int c = (k >> 3) ^ ((n >> 1) & 3);
    return (uint32_t)(n * 64 + c * 16 + (k & 7) * 2);
}
__device__ __forceinline__ uint32_t aswz(int r, int k) {
    int cc = k >> 3;
    int ccp = (cc & 24) | ((cc ^ r) & 7);
    return (uint32_t)(r * 512 + ccp * 16 + (k & 7) * 2);
}

// ---------------------------------------------------------------------------
// Aggregation pipeline (counting sort by dst, then gather-aggregate)
// ---------------------------------------------------------------------------
// init16 also zeros the histogram counters
__global__ void k_init16(const float* __restrict__ x) {
    int i = blockIdx.x * blockDim.x + threadIdx.x;
    if (i < N_NODES) g_cnt[i] = 0;
    if (i < N_NODES * 16) {
        float4 v = reinterpret_cast<const float4*>(x)[i];
        __half2 h0 = __floats2half2_rn(v.x, v.y);
        __half2 h1 = __floats2half2_rn(v.z, v.w);
        uint2 p;
        memcpy(&p.x, &h0, 4);
        memcpy(&p.y, &h1, 4);
        reinterpret_cast<uint2*>(g_x16)[i] = p;
    }
}

__global__ void k_hist(const int* __restrict__ ei) {
    int e = blockIdx.x * blockDim.x + threadIdx.x;
    if (e < N_EDGES) atomicAdd(&g_cnt[__ldg(ei + N_EDGES + e)], 1);
}

// Scan step 1: per-block (1024) exclusive prefix + block totals
__global__ void k_scan1() {
    __shared__ int sh[1024];
    int tid = threadIdx.x;
    int i = blockIdx.x * 1024 + tid;
    int v = (i < N_NODES) ? g_cnt[i] : 0;
    sh[tid] = v;
    __syncthreads();
    #pragma unroll
    for (int d = 1; d < 1024; d <<= 1) {
        int t = (tid >= d) ? sh[tid - d] : 0;
        __syncthreads();
        sh[tid] += t;
        __syncthreads();
    }
    if (i < N_NODES) g_off[i] = sh[tid] - v;     // exclusive within block
    if (tid == 1023) g_part[blockIdx.x] = sh[1023];
}

// Scan step 2: exclusive scan of 98 block totals (single block)
__global__ void k_scan2() {
    __shared__ int sh[128];
    int tid = threadIdx.x;
    if (tid < 98) sh[tid] = g_part[tid];
    __syncthreads();
    if (tid == 0) {
        int run = 0;
        for (int i = 0; i < 98; i++) { int t = sh[i]; sh[i] = run; run += t; }
    }
    __syncthreads();
    if (tid < 98) g_part[tid] = sh[tid];
}

// Scan step 3: add block offsets; init fill pointers
__global__ void k_scan3() {
    int i = blockIdx.x * blockDim.x + threadIdx.x;
    if (i < N_NODES) {
        int o = g_off[i] + g_part[i >> 10];
        g_off[i] = o;
        g_pos[i] = o;
    }
}

__global__ void k_reorder(const int* __restrict__ ei) {
    int e = blockIdx.x * blockDim.x + threadIdx.x;
    if (e < N_EDGES) {
        int src = __ldg(ei + e);
        int dst = __ldg(ei + N_EDGES + e);
        int pos = atomicAdd(&g_pos[dst], 1);
        g_sorted[pos] = src;
    }
}

// One warp per node. Grouped gather: lane-group g8 = lane>>3 handles edges
// j+g8; each lane loads uint4 (16B) so 8 lanes cover a 128B fp16 row -> one
// LDG.128 warp-instruction gathers 4 edges. Per-lane f[8] fp32 accumulators
// (cols c8*8..c8*8+7); shfl_xor(8,16) folds the 4 groups; lanes 0-7 store.
__global__ __launch_bounds__(256) void k_aggregate(const float* __restrict__ x) {
    int n = blockIdx.x * 8 + (threadIdx.x >> 5);   // 12500*8 = 100000 exactly
    int lane = threadIdx.x & 31;
    int g8 = lane >> 3;          // edge-group 0..3
    int c8 = lane & 7;           // column-slice (cols c8*8 .. c8*8+7)
    int off = g_off[n];
    int cnt = g_cnt[n];
    float f[8];
    #pragma unroll
    for (int i = 0; i < 8; i++) f[i] = 0.f;
    const uint4* xr = (const uint4*)g_x16;   // row = 8 uint4

    for (int base = 0; base < cnt; base += 32) {
        int rem = cnt - base; if (rem > 32) rem = 32;
        int s = (lane < rem) ? __ldg(g_sorted + off + base + lane) : 0;
        for (int j = 0; j < rem; j += 8) {
            int e0 = j + g8;
            int e1 = j + 4 + g8;
            int s0 = __shfl_sync(0xffffffffu, s, e0 & 31);
            int s1 = __shfl_sync(0xffffffffu, s, e1 & 31);
            uint4 p0 = make_uint4(0u, 0u, 0u, 0u);
            uint4 p1 = make_uint4(0u, 0u, 0u, 0u);
            if (e0 < rem) p0 = __ldg(xr + (size_t)s0 * 8 + c8);
            if (e1 < rem) p1 = __ldg(xr + (size_t)s1 * 8 + c8);
            const uint32_t* u0 = (const uint32_t*)&p0;
            const uint32_t* u1 = (const uint32_t*)&p1;
            #pragma unroll
            for (int u = 0; u < 4; u++) {
                __half2 h; float2 ff;
                memcpy(&h, &u0[u], 4); ff = __half22float2(h);
                f[2 * u] += ff.x; f[2 * u + 1] += ff.y;
                memcpy(&h, &u1[u], 4); ff = __half22float2(h);
                f[2 * u] += ff.x; f[2 * u + 1] += ff.y;
            }
        }
    }
    // fold the 4 edge-groups (lanes k, k+8, k+16, k+24 share a column slice)
    #pragma unroll
    for (int d = 8; d <= 16; d <<= 1)
        #pragma unroll
        for (int i = 0; i < 8; i++)
            f[i] += __shfl_xor_sync(0xffffffffu, f[i], d);

    if (g8 == 0) {   // lanes 0..7 each store 8 cols (32 B) -> full 256 B row
        const float4* xv = (const float4*)(x + (size_t)n * 64 + c8 * 8);
        float4 xa = __ldg(xv), xb = __ldg(xv + 1);
        float4 r0 = make_float4(f[0] + xa.x, f[1] + xa.y, f[2] + xa.z, f[3] + xa.w);
        float4 r1 = make_float4(f[4] + xb.x, f[5] + xb.y, f[6] + xb.z, f[7] + xb.w);
        float4* d = (float4*)(g_aggr + (size_t)n * 64 + c8 * 8);
        d[0] = r0;
        d[1] = r1;
    }
}

// ---------------------------------------------------------------------------
// Prep: weights -> fp16 hi swizzled chunk images; fold BN
// ---------------------------------------------------------------------------
__global__ void k_prep(const float* __restrict__ W1, const float* __restrict__ W2,
    const float* __restrict__ b1, const float* __restrict__ g1, const float* __restrict__ be1,
    const float* __restrict__ rm1, const float* __restrict__ rv1,
    const float* __restrict__ b2, const float* __restrict__ g2, const float* __restrict__ be2,
    const float* __restrict__ rm2, const float* __restrict__ rv2)
{
    int t = blockIdx.x * 256 + threadIdx.x;
    if (t < 81920) {
        int ci = t >> 13;          // chunk 0..9
        int r  = t & 8191;
        int n  = r >> 5;           // 0..255
        int kl = r & 31;           // 0..31
        float v;
        if (ci < 2) v = W1[(size_t)(ci * 32 + kl) * 256 + n];
        else        v = W2[(size_t)((ci - 2) * 32 + kl) * 256 + n];
        unsigned char* base = g_Wimg + (size_t)ci * 16384;
        *(__half*)(base + bswz(n, kl)) = __float2half_rn(v);
    } else if (t < 82432) {
        int i = t - 81920;
        int n = i & 255;
        if (i < 256) { float s = g1[n] * rsqrtf(rv1[n] + BN_EPS); g_s1[n] = s; g_o1[n] = (b1[n] - rm1[n]) * s + be1[n]; }
        else         { float s = g2[n] * rsqrtf(rv2[n] + BN_EPS); g_s2[n] = s; g_o2[n] = (b2[n] - rm2[n]) * s + be2[n]; }
    }
}

// ---------------------------------------------------------------------------
// PTX helpers (arch-agnostic sm_80+)
// ---------------------------------------------------------------------------
__device__ __forceinline__ uint32_t s2u(const void* p) {
    uint32_t a;
    asm("{ .reg .u64 t; cvta.to.shared.u64 t, %1; cvt.u32.u64 %0, t; }" : "=r"(a) : "l"(p));
    return a;
}
__device__ __forceinline__ void ldm4(uint32_t* r, uint32_t addr) {
    asm volatile("ldmatrix.sync.aligned.m8n8.x4.shared.b16 {%0,%1,%2,%3}, [%4];"
                 : "=r"(r[0]), "=r"(r[1]), "=r"(r[2]), "=r"(r[3]) : "r"(addr));
}
__device__ __forceinline__ void mma_f16(float* c, const uint32_t* a, uint32_t b0, uint32_t b1) {
    asm volatile(
        "mma.sync.aligned.m16n8k16.row.col.f32.f16.f16.f32 "
        "{%0,%1,%2,%3}, {%4,%5,%6,%7}, {%8,%9}, {%0,%1,%2,%3};"
        : "+f"(c[0]), "+f"(c[1]), "+f"(c[2]), "+f"(c[3])
        : "r"(a[0]), "r"(a[1]), "r"(a[2]), "r"(a[3]), "r"(b0), "r"(b1));
}
__device__ __forceinline__ void cpa16(uint32_t s, const void* g) {
    asm volatile("cp.async.cg.shared.global [%0], [%1], 16;" :: "r"(s), "l"(g));
}
#define CP_COMMIT() asm volatile("cp.async.commit_group;" ::: "memory")

// fp16 hi/lo split of a pair of floats, packed as half2 words
__device__ __forceinline__ void split_pack(float a, float b, uint32_t& hi, uint32_t& lo) {
    __half ah = __float2half_rn(a), bh = __float2half_rn(b);
    float ar = a - __half2float(ah);
    float br = b - __half2float(bh);
    __half2 hp = __halves2half2(ah, bh);   // low half = a
    __half2 lp = __floats2half2_rn(ar, br);
    memcpy(&hi, &hp, 4);
    memcpy(&lo, &lp, 4);
}

// ---------------------------------------------------------------------------
// Kernel: fp16 mma.sync MLP. 2-term (hi+lo A) layer 1, single-term layer 2.
// CTA = 64 nodes x 256 cols, 256 threads (8 warps), 2 CTAs/SM.
// ---------------------------------------------------------------------------
#define H_LO     32768
#define OFF_B0   65536
#define STAGE_SZ 16384
#define SMEM_REQ (114688 + 128)

__global__ __launch_bounds__(256, 2) void k_mlp6(float* __restrict__ out) {
    extern __shared__ unsigned char dyn[];
    uint32_t raw = s2u(dyn);
    uint32_t sb  = (raw + 127u) & ~127u;
    unsigned char* sp = dyn + (sb - raw);

    const int tid  = threadIdx.x;
    const int lane = tid & 31;
    const int w    = tid >> 5;
    const int m_w  = (w >> 2) * 32;
    const int n_w  = (w & 3) * 64;
    const int lr   = lane & 7, lsel = lane >> 3;
    const int arow = lr + (lsel & 1) * 8, acol8 = (lsel >> 1) * 8;
    const int brow = lr + (lsel >> 1) * 8, bcol8 = (lsel & 1) * 8;
    const int gid  = lane >> 2, tg2 = (lane & 3) * 2;
    const int row0 = blockIdx.x * 64;

    // ---- prologue: prefetch chunks 0,1 into stages 0,1 (16KB each) ----
    #pragma unroll
    for (int j = 0; j < 4; j++)
        cpa16(sb + OFF_B0 + (tid + 256 * j) * 16, g_Wimg + (tid + 256 * j) * 16);
    CP_COMMIT();
    #pragma unroll
    for (int j = 0; j < 4; j++)
        cpa16(sb + OFF_B0 + STAGE_SZ + (tid + 256 * j) * 16,
              g_Wimg + STAGE_SZ + (tid + 256 * j) * 16);
    CP_COMMIT();

    // ---- load h tile [64][64] f32 -> fp16 hi/lo into A/H planes ----
    {
        int rr = tid >> 2, q = tid & 3;
        float4 f[4];
        #pragma unroll
        for (int i = 0; i < 4; i++) {
            f[i] = make_float4(0.f, 0.f, 0.f, 0.f);
            if (row0 + rr < N_NODES)
                f[i] = ((const float4*)g_aggr)[(size_t)(row0 + rr) * 16 + q * 4 + i];
        }
        uint32_t hi[8], lo[8];
        #pragma unroll
        for (int i = 0; i < 4; i++) {
            split_pack(f[i].x, f[i].y, hi[2 * i],     lo[2 * i]);
            split_pack(f[i].z, f[i].w, hi[2 * i + 1], lo[2 * i + 1]);
        }
        uint32_t o0 = aswz(rr, q * 16);
        uint32_t o1 = aswz(rr, q * 16 + 8);
        *(uint4*)(sp + o0)        = ((uint4*)hi)[0];
        *(uint4*)(sp + o1)        = ((uint4*)hi)[1];
        *(uint4*)(sp + H_LO + o0) = ((uint4*)lo)[0];
        *(uint4*)(sp + H_LO + o1) = ((uint4*)lo)[1];
    }

    float acc[2][8][4];
    #pragma unroll
    for (int a = 0; a < 2; a++)
        #pragma unroll
        for (int b = 0; b < 8; b++)
            #pragma unroll
            for (int cq = 0; cq < 4; cq++) acc[a][b][cq] = 0.f;

    for (int i = 0; i < 10; i++) {
        if (i < 9) asm volatile("cp.async.wait_group 1;" ::: "memory");
        else       asm volatile("cp.async.wait_group 0;" ::: "memory");
        __syncthreads();

        if (i + 2 <= 9) {
            const unsigned char* g = g_Wimg + (size_t)(i + 2) * STAGE_SZ;
            uint32_t s = sb + OFF_B0 + ((i + 2) % 3) * STAGE_SZ;
            #pragma unroll
            for (int j = 0; j < 4; j++)
                cpa16(s + (tid + 256 * j) * 16, g + (tid + 256 * j) * 16);
            CP_COMMIT();
        }

        const bool l1 = (i < 2);
        const int kA0 = l1 ? i * 32 : (i - 2) * 32;
        const uint32_t bbuf = sb + OFF_B0 + (i % 3) * STAGE_SZ;

        #pragma unroll
        for (int step = 0; step < 2; step++) {
            const int kA = kA0 + step * 16;
            const int kB = step * 16;
            uint32_t Ah[2][4], Al[2][4], Bb[4][4];
            #pragma unroll
            for (int mt = 0; mt < 2; mt++)
                ldm4(Ah[mt], sb + aswz(m_w + mt * 16 + arow, kA + acol8));
            if (l1) {
                #pragma unroll
                for (int mt = 0; mt < 2; mt++)
                    ldm4(Al[mt], sb + H_LO + aswz(m_w + mt * 16 + arow, kA + acol8));
            }
            #pragma unroll
            for (int np = 0; np < 4; np++)
                ldm4(Bb[np], bbuf + bswz(n_w + np * 16 + brow, kB + bcol8));
            // hi * hi
            #pragma unroll
            for (int mt = 0; mt < 2; mt++)
                #pragma unroll
                for (int np = 0; np < 4; np++) {
                    mma_f16(acc[mt][np * 2],     Ah[mt], Bb[np][0], Bb[np][1]);
                    mma_f16(acc[mt][np * 2 + 1], Ah[mt], Bb[np][2], Bb[np][3]);
                }
            // lo * hi (layer 1 only)
            if (l1) {
                #pragma unroll
                for (int mt = 0; mt < 2; mt++)
                    #pragma unroll
                    for (int np = 0; np < 4; np++) {
                        mma_f16(acc[mt][np * 2],     Al[mt], Bb[np][0], Bb[np][1]);
                        mma_f16(acc[mt][np * 2 + 1], Al[mt], Bb[np][2], Bb[np][3]);
                    }
            }
        }

        if (i == 1) {
            __syncthreads();
            // ---- epilogue 1: BN1 + ReLU -> H1 hi plane only, reset acc ----
            #pragma unroll
            for (int nt = 0; nt < 8; nt++) {
                int col = n_w + nt * 8 + tg2;
                float2 s = *(const float2*)(g_s1 + col);
                float2 o = *(const float2*)(g_o1 + col);
                #pragma unroll
                for (int mt = 0; mt < 2; mt++) {
                    float* c = acc[mt][nt];
                    __half2 p0 = __floats2half2_rn(fmaxf(c[0] * s.x + o.x, 0.f),
                                                   fmaxf(c[1] * s.y + o.y, 0.f));
                    __half2 p1 = __floats2half2_rn(fmaxf(c[2] * s.x + o.x, 0.f),
                                                   fmaxf(c[3] * s.y + o.y, 0.f));
                    uint32_t h0, h1;
                    memcpy(&h0, &p0, 4);
                    memcpy(&h1, &p1, 4);
                    int r0 = m_w + mt * 16 + gid;
                    *(uint32_t*)(sp + aswz(r0, col))     = h0;
                    *(uint32_t*)(sp + aswz(r0 + 8, col)) = h1;
                    c[0] = c[1] = c[2] = c[3] = 0.f;
                }
            }
        }
    }

    // ---- epilogue 2: BN2 + ReLU, staged coalesced stores ----
    float* stageF = (float*)(sp + OFF_B0);
    for (int q = 0; q < 2; q++) {
        __syncthreads();
        if ((w >> 2) == q) {
            #pragma unroll
            for (int nt = 0; nt < 8; nt++) {
                int col = n_w + nt * 8 + tg2;
                float2 s = *(const float2*)(g_s2 + col);
                float2 o = *(const float2*)(g_o2 + col);
                #pragma unroll
                for (int mt = 0; mt < 2; mt++) {
                    float* c = acc[mt][nt];
                    int r = mt * 16 + gid;
                    *(float2*)(stageF + r * 260 + col) =
                        make_float2(fmaxf(c[0] * s.x + o.x, 0.f),
                                    fmaxf(c[1] * s.y + o.y, 0.f));
                    *(float2*)(stageF + (r + 8) * 260 + col) =
                        make_float2(fmaxf(c[2] * s.x + o.x, 0.f),
                                    fmaxf(c[3] * s.y + o.y, 0.f));
                }
            }
        }
        __syncthreads();
        #pragma unroll
        for (int j = 0; j < 8; j++) {
            int idx = tid + 256 * j;
            int rr = idx >> 6, c4 = idx & 63;
            int grow = row0 + q * 32 + rr;
            if (grow < N_NODES)
                ((float4*)out)[(size_t)grow * 64 + c4] =
                    *(float4*)(stageF + rr * 260 + c4 * 4);
        }
    }
}

// ---------------------------------------------------------------------------
// Launch
// ---------------------------------------------------------------------------
extern "C" void kernel_launch(void* const* d_in, const int* in_sizes, int n_in,
                              void* d_out, int out_size) {
    const float* x   = (const float*)d_in[0];
    const int*   ei  = (const int*)  d_in[2];
    const float* W1  = (const float*)d_in[3];
    const float* b1  = (const float*)d_in[4];
    const float* g1  = (const float*)d_in[5];
    const float* be1 = (const float*)d_in[6];
    const float* rm1 = (const float*)d_in[7];
    const float* rv1 = (const float*)d_in[8];
    const float* W2  = (const float*)d_in[9];
    const float* b2  = (const float*)d_in[10];
    const float* g2  = (const float*)d_in[11];
    const float* be2 = (const float*)d_in[12];
    const float* rm2 = (const float*)d_in[13];
    const float* rv2 = (const float*)d_in[14];
    float* out = (float*)d_out;

    k_init16<<<(N_NODES * 16 + 255) / 256, 256>>>(x);   // also zeros g_cnt
    k_hist<<<N_EDGES / 256, 256>>>(ei);
    k_prep<<<322, 256>>>(W1, W2, b1, g1, be1, rm1, rv1, b2, g2, be2, rm2, rv2);
    k_scan1<<<98, 1024>>>();
    k_scan2<<<1, 128>>>();
    k_scan3<<<(N_NODES + 255) / 256, 256>>>();
    k_reorder<<<N_EDGES / 256, 256>>>(ei);
    k_aggregate<<<N_NODES / 8, 256>>>(x);

    {
        cudaFuncSetAttribute(k_mlp6, cudaFuncAttributeMaxDynamicSharedMemorySize,
                             SMEM_REQ);
        int blocks = (N_NODES + 63) / 64;   // 1563
        k_mlp6<<<blocks, 256, SMEM_REQ>>>(out);
    }
    (void)in_sizes; (void)n_in; (void)out_size;
}